// round 10
// baseline (speedup 1.0000x reference)
#include <cuda_runtime.h>
#include <cuda_bf16.h>
#include <math.h>

namespace {

constexpr int NVc = 32;   // x dim
constexpr int MCc = 24;   // constraint rows in A
constexpr int MHc = 20;   // hard rows
constexpr int ITc = 200;  // ADMM iterations (must match reference trajectory)

// per-warp shared layout (floats)
constexpr int OFF_A = 0;            // A: 24 rows, stride 36
constexpr int OFF_M = 864;          // M workspace: 32 x 36
constexpr int OFF_T = 2160;         // t1 buffer (28)
constexpr int OFF_R = 2192;         // rhs (32, pad 40); also GJ pivot-row buffer
constexpr int OFF_U = 2232;         // x_feas for gradient (32, pad 40)
constexpr int WARPF = 2304;         // 9216 bytes per warp

using ull = unsigned long long;

// ---- packed f32x2 helpers (Blackwell FFMA2 path, PTX-only) ----
__device__ __forceinline__ ull pk2(float lo, float hi) {
    ull r;
    asm("mov.b64 %0, {%1, %2};" : "=l"(r) : "f"(lo), "f"(hi));
    return r;
}
__device__ __forceinline__ float2 upk2(ull v) {
    float lo, hi;
    asm("mov.b64 {%0, %1}, %2;" : "=f"(lo), "=f"(hi) : "l"(v));
    return make_float2(lo, hi);
}
__device__ __forceinline__ ull ffma2(ull a, ull b, ull c) {
    ull d;
    asm("fma.rn.f32x2 %0, %1, %2, %3;" : "=l"(d) : "l"(a), "l"(b), "l"(c));
    return d;
}

// Register-resident Gauss-Jordan inverse of SPD 32x32: lane tid owns row tid.
// buf = 32-float, 16B-aligned smem scratch for pivot-row broadcast.
__device__ __forceinline__ void gj_inv_reg(float row[32], float* buf, int tid) {
#pragma unroll
    for (int k = 0; k < 32; ++k) {
        if (tid == k) {
            float4* b4 = reinterpret_cast<float4*>(buf);
#pragma unroll
            for (int q = 0; q < 8; q++)
                b4[q] = make_float4(row[4 * q], row[4 * q + 1], row[4 * q + 2], row[4 * q + 3]);
        }
        __syncwarp();
        float rk[32];
        {
            const float4* b4 = reinterpret_cast<const float4*>(buf);
#pragma unroll
            for (int q = 0; q < 8; q++) {
                float4 v = b4[q];
                rk[4 * q] = v.x; rk[4 * q + 1] = v.y; rk[4 * q + 2] = v.z; rk[4 * q + 3] = v.w;
            }
        }
        __syncwarp();
        float piv = 1.0f / rk[k];
        float f = (row[k] - ((tid == k) ? 1.0f : 0.0f)) * piv;
#pragma unroll
        for (int j = 0; j < 32; ++j)
            row[j] = fmaf(-f, rk[j], row[j]);
        row[k] = (tid == k) ? piv : -f;
    }
}

__global__ void __launch_bounds__(128, 5)
fw_kernel(const float* __restrict__ x_raw, const float* __restrict__ Ain,
          const float* __restrict__ bin, const float* __restrict__ W1,
          const float* __restrict__ b1v, const float* __restrict__ w2,
          float* __restrict__ out, int P)
{
    __shared__ __align__(16) float smem_all[4 * WARPF];
    const int tid = threadIdx.x & 31;
    const int wid = threadIdx.x >> 5;
    const int p = blockIdx.x * 4 + wid;
    if (p >= P) return;
    float* sw = smem_all + wid * WARPF;

    // ------------------------------------------------------------------
    // Load A (smem rows + packed lane-column apk), b, x_raw
    // ------------------------------------------------------------------
    ull apk[12];   // packed pairs (A[2j][tid], A[2j+1][tid])
    {
        float tmpA[MCc];
        const float* Ap = Ain + (size_t)p * (MCc * NVc);
#pragma unroll
        for (int r = 0; r < MCc; r++) {
            float v = Ap[r * NVc + tid];
            sw[OFF_A + r * 36 + tid] = v;
            tmpA[r] = v;
        }
#pragma unroll
        for (int j = 0; j < 12; j++) apk[j] = pk2(tmpA[2 * j], tmpA[2 * j + 1]);
    }
    const float b_own = (tid < MCc) ? bin[(size_t)p * MCc + tid] : 0.0f;
    const float xr = x_raw[(size_t)p * NVc + tid];
    __syncwarp();

    float xf_own = 0.0f, u_own = 0.0f, g_own = 0.0f;

    // ==================================================================
    //  phase 0: anchor QP (Schur-reduced, Ks = A_h^T A_h + .75 A_s^T A_s + 2I)
    //  phase 1: LMO LP   (K = A^T A + I), preceded by the critic gradient
    // ==================================================================
#pragma unroll 1
    for (int phase = 0; phase < 2; ++phase) {
        if (phase == 1) {
            // ----------------------------------------------------------
            // Gradient of critic: g = W1 @ (w2 * (1 - tanh^2(x W1 + b1)))
            // ----------------------------------------------------------
            float gp[32];
#pragma unroll
            for (int j = 0; j < 32; j++) gp[j] = 0.0f;
#pragma unroll 1
            for (int hb = 0; hb < 8; ++hb) {
                int h = hb * 32 + tid;
                float col[32];
#pragma unroll
                for (int j = 0; j < 32; j++) col[j] = W1[j * 256 + h];
                float z0 = b1v[h], z1 = 0.0f;
                const float4* x4 = reinterpret_cast<const float4*>(sw + OFF_U);
#pragma unroll
                for (int q = 0; q < 8; q++) {
                    float4 xv = x4[q];
                    float s = xv.x * col[4 * q] + xv.y * col[4 * q + 1]
                            + xv.z * col[4 * q + 2] + xv.w * col[4 * q + 3];
                    if (q & 1) z1 += s; else z0 += s;
                }
                float th = tanhf(z0 + z1);
                float v = w2[h] * (1.0f - th * th);
#pragma unroll
                for (int j = 0; j < 32; j++) gp[j] = fmaf(v, col[j], gp[j]);
            }
            __syncwarp();
            {
                float4* md = reinterpret_cast<float4*>(sw + OFF_M + tid * 36);
#pragma unroll
                for (int q = 0; q < 8; q++)
                    md[q] = make_float4(gp[4 * q], gp[4 * q + 1], gp[4 * q + 2], gp[4 * q + 3]);
            }
            __syncwarp();
            float gs0 = 0.0f, gs1 = 0.0f;
#pragma unroll
            for (int i = 0; i < 32; i++) {
                float v = sw[OFF_M + i * 36 + tid];
                if (i & 1) gs1 += v; else gs0 += v;
            }
            g_own = gs0 + gs1;
            __syncwarp();   // OFF_M reads done before it is overwritten below
        }

        // --------------------------------------------------------------
        // Build K row in registers (a read from smem), invert in regs
        // --------------------------------------------------------------
        float mrow[32];
        {
            const float dg = (phase == 0) ? 2.0f : 1.0f;
            const float ws = (phase == 0) ? 0.75f : 1.0f;
#pragma unroll
            for (int e = 0; e < 32; e++) mrow[e] = (tid == e) ? dg : 0.0f;
#pragma unroll
            for (int r = 0; r < MCc; r++) {
                float a = sw[OFF_A + r * 36 + tid];
                if (r >= MHc) a *= ws;
                const float4* ar = reinterpret_cast<const float4*>(sw + OFF_A + r * 36);
#pragma unroll
                for (int q = 0; q < 8; q++) {
                    float4 v = ar[q];
                    mrow[4 * q + 0] = fmaf(a, v.x, mrow[4 * q + 0]);
                    mrow[4 * q + 1] = fmaf(a, v.y, mrow[4 * q + 1]);
                    mrow[4 * q + 2] = fmaf(a, v.z, mrow[4 * q + 2]);
                    mrow[4 * q + 3] = fmaf(a, v.w, mrow[4 * q + 3]);
                }
            }
        }

        gj_inv_reg(mrow, sw + OFF_R, tid);   // mrow = Kinv row tid

        // write Kinv rows to smem once (GM build needs all rows)
        {
            float4* md = reinterpret_cast<float4*>(sw + OFF_M + tid * 36);
#pragma unroll
            for (int q = 0; q < 8; q++)
                md[q] = make_float4(mrow[4 * q], mrow[4 * q + 1], mrow[4 * q + 2], mrow[4 * q + 3]);
        }
        __syncwarp();

        // --------------------------------------------------------------
        // GM row = coef * (A_src * Kinv)
        // --------------------------------------------------------------
        float GM[32];
        {
            bool act; float coef; int src;
            if (phase == 0) {
                act = (tid < 28);
                coef = (tid < MHc) ? 1.0f : (tid < MCc) ? 0.75f : -0.25f;
                src = (tid < MCc) ? tid : tid - 4;
            } else {
                act = (tid < MCc);
                coef = 1.0f;
                src = tid;
            }
#pragma unroll
            for (int e = 0; e < 32; e++) GM[e] = 0.0f;
#pragma unroll 1
            for (int jb = 0; jb < 8; jb++) {
                float4 av = make_float4(0.f, 0.f, 0.f, 0.f);
                if (act)
                    av = reinterpret_cast<const float4*>(sw + OFF_A + src * 36)[jb];
                av.x *= coef; av.y *= coef; av.z *= coef; av.w *= coef;
#pragma unroll
                for (int c = 0; c < 4; c++) {
                    int j = 4 * jb + c;
                    float a = (c == 0) ? av.x : (c == 1) ? av.y : (c == 2) ? av.z : av.w;
                    const float4* mrw = reinterpret_cast<const float4*>(sw + OFF_M + j * 36);
#pragma unroll
                    for (int q = 0; q < 8; q++) {
                        float4 v = mrw[q];
                        GM[4 * q + 0] = fmaf(a, v.x, GM[4 * q + 0]);
                        GM[4 * q + 1] = fmaf(a, v.y, GM[4 * q + 1]);
                        GM[4 * q + 2] = fmaf(a, v.z, GM[4 * q + 2]);
                        GM[4 * q + 3] = fmaf(a, v.w, GM[4 * q + 3]);
                    }
                }
            }
        }

        // pack Kinv row + GM row into f32x2 pairs; scalars die here
        ull mpk[16], gpk[16];
#pragma unroll
        for (int c = 0; c < 16; c++) {
            mpk[c] = pk2(mrow[2 * c], mrow[2 * c + 1]);
            gpk[c] = pk2(GM[2 * c], GM[2 * c + 1]);
        }

        // --------------------------------------------------------------
        // ADMM loops (packed FFMA2 dots)
        // --------------------------------------------------------------
        if (phase == 0) {
            // Anchor: rows 0..27 (y1,t1) on lanes 0..27; rows 28..59 per-lane
            float2 pa = upk2(apk[10]), pb = upk2(apk[11]);
            const float Ac20 = pa.x, Ac21 = pa.y, Ac22 = pb.x, Ac23 = pb.y;
            float y1 = 0.0f, t1o = 0.0f, y3 = 0.0f, t3o = 0.0f;
            u_own = 0.0f;
            const float h1 = (tid < MCc) ? b_own : 0.0f;
            if (tid < 28) sw[OFF_T + tid] = 0.0f;
            float r2_own = 0.0f;
#pragma unroll 1
            for (int it = 0; it <= ITc; ++it) {
                __syncwarp();
                {
                    const ulonglong2* t2 = reinterpret_cast<const ulonglong2*>(sw + OFF_T);
                    ull ac0 = 0ull, ac1 = 0ull;
#pragma unroll
                    for (int q = 0; q < 5; q++) {
                        ulonglong2 tv = t2[q];
                        ac0 = ffma2(apk[2 * q], tv.x, ac0);
                        ac1 = ffma2(apk[2 * q + 1], tv.y, ac1);
                    }
                    const float4* t4 = reinterpret_cast<const float4*>(sw + OFF_T);
                    float4 tv5 = t4[5], tv6 = t4[6];
                    float r2x = -tv5.x - tv6.x;
                    float r2y = -tv5.y - tv6.y;
                    float r2z = -tv5.z - tv6.z;
                    float r2w = -tv5.w - tv6.w;
                    int k = tid & 3;
                    r2_own = (k == 0) ? r2x : (k == 1) ? r2y : (k == 2) ? r2z : r2w;
                    float2 s0 = upk2(ac0), s1 = upk2(ac1);
                    float a0 = xr + s0.x + s0.y + s1.x + s1.y;
                    a0 += Ac20 * (tv5.x + 0.25f * r2x) + Ac21 * (tv5.y + 0.25f * r2y)
                        + Ac22 * (tv5.z + 0.25f * r2z) + Ac23 * (tv5.w + 0.25f * r2w);
                    sw[OFF_R + tid] = a0 - t3o;
                }
                __syncwarp();
                float gu;
                {
                    const ulonglong2* rv2 = reinterpret_cast<const ulonglong2*>(sw + OFF_R);
                    ull au0 = 0ull, au1 = 0ull, ag0 = 0ull, ag1 = 0ull;
#pragma unroll
                    for (int q = 0; q < 8; q++) {
                        ulonglong2 rv = rv2[q];
                        au0 = ffma2(mpk[2 * q], rv.x, au0);
                        au1 = ffma2(mpk[2 * q + 1], rv.y, au1);
                        ag0 = ffma2(gpk[2 * q], rv.x, ag0);
                        ag1 = ffma2(gpk[2 * q + 1], rv.y, ag1);
                    }
                    float2 ua = upk2(au0), ub = upk2(au1), ga = upk2(ag0), gb = upk2(ag1);
                    u_own = ua.x + ua.y + ub.x + ub.y;
                    gu = ga.x + ga.y + gb.x + gb.y;
                    if (tid >= MHc) gu -= 0.25f * r2_own;
                }
                if (it == ITc) break;
                float w = gu + y1;
                float z = fminf(w, h1);
                y1 = w - z;
                t1o = z - y1;
                if (tid < 28) sw[OFF_T + tid] = t1o;
                float w3 = y3 - u_own;
                float z3 = fminf(w3, 0.0f);
                y3 = w3 - z3;
                t3o = z3 - y3;
            }
            xf_own = u_own;
            sw[OFF_U + tid] = u_own;
            __syncwarp();
        } else {
            // LMO: rows 0..23 (A, h=b) on lanes 0..23; rows 24..55 per-lane
            float y1 = 0.0f, t1o = 0.0f, y3 = 0.0f, t3o = 0.0f;
            u_own = 0.0f;
            if (tid < MCc) sw[OFF_T + tid] = 0.0f;
#pragma unroll 1
            for (int it = 0; it <= ITc; ++it) {
                __syncwarp();
                {
                    const ulonglong2* t2 = reinterpret_cast<const ulonglong2*>(sw + OFF_T);
                    ull ac0 = 0ull, ac1 = 0ull;
#pragma unroll
                    for (int q = 0; q < 6; q++) {
                        ulonglong2 tv = t2[q];
                        ac0 = ffma2(apk[2 * q], tv.x, ac0);
                        ac1 = ffma2(apk[2 * q + 1], tv.y, ac1);
                    }
                    float2 s0 = upk2(ac0), s1 = upk2(ac1);
                    sw[OFF_R + tid] = g_own + s0.x + s0.y + s1.x + s1.y - t3o;
                }
                __syncwarp();
                {
                    const ulonglong2* rv2 = reinterpret_cast<const ulonglong2*>(sw + OFF_R);
                    ull au0 = 0ull, au1 = 0ull, ag0 = 0ull, ag1 = 0ull;
#pragma unroll
                    for (int q = 0; q < 8; q++) {
                        ulonglong2 rv = rv2[q];
                        au0 = ffma2(mpk[2 * q], rv.x, au0);
                        au1 = ffma2(mpk[2 * q + 1], rv.y, au1);
                        ag0 = ffma2(gpk[2 * q], rv.x, ag0);
                        ag1 = ffma2(gpk[2 * q + 1], rv.y, ag1);
                    }
                    float2 ua = upk2(au0), ub = upk2(au1), ga = upk2(ag0), gb = upk2(ag1);
                    u_own = ua.x + ua.y + ub.x + ub.y;
                    float gu = ga.x + ga.y + gb.x + gb.y;
                    if (it == ITc) break;
                    float w = gu + y1;
                    float z = fminf(w, b_own);
                    y1 = w - z;
                    t1o = z - y1;
                    if (tid < MCc) sw[OFF_T + tid] = t1o;
                    float w3 = y3 - u_own;
                    float z3 = fminf(w3, 0.0f);
                    y3 = w3 - z3;
                    t3o = z3 - y3;
                }
            }
        }
    }

    // Frank-Wolfe blend
    out[(size_t)p * NVc + tid] = 0.9f * xf_own + 0.1f * u_own;
}

}  // namespace

extern "C" void kernel_launch(void* const* d_in, const int* in_sizes, int n_in,
                              void* d_out, int out_size) {
    const float* x_raw = (const float*)d_in[0];
    const float* A     = (const float*)d_in[1];
    const float* b     = (const float*)d_in[2];
    const float* W1    = (const float*)d_in[3];
    const float* b1v   = (const float*)d_in[4];
    const float* w2    = (const float*)d_in[5];
    float* out = (float*)d_out;
    int P = in_sizes[0] / 32;           // number of flattened problems
    int blocks = (P + 3) / 4;           // 4 problems (warps) per block
    fw_kernel<<<blocks, 128>>>(x_raw, A, b, W1, b1v, w2, out, P);
}

// round 11
// speedup vs baseline: 2.0429x; 2.0429x over previous
#include <cuda_runtime.h>
#include <cuda_bf16.h>
#include <math.h>

namespace {

constexpr int NVc = 32;   // x dim
constexpr int MCc = 24;   // constraint rows in A
constexpr int MHc = 20;   // hard rows
constexpr int ITc = 200;  // ADMM iterations (must match reference trajectory)

// per-warp shared layout (floats)
constexpr int OFF_A = 0;            // A: 24 rows, stride 36
constexpr int OFF_M = 864;          // M workspace: 32 x 36
constexpr int OFF_T = 2160;         // t buffer (24 used, pad 32)
constexpr int OFF_R = 2192;         // rhs (32, pad 40); also GJ pivot-row buffer
constexpr int OFF_U = 2232;         // x_feas for gradient (32, pad 40)
constexpr int WARPF = 2304;         // 9216 bytes per warp

using ull = unsigned long long;

// ---- packed f32x2 helpers (Blackwell FFMA2 path, PTX-only) ----
__device__ __forceinline__ ull pk2(float lo, float hi) {
    ull r;
    asm("mov.b64 %0, {%1, %2};" : "=l"(r) : "f"(lo), "f"(hi));
    return r;
}
__device__ __forceinline__ float2 upk2(ull v) {
    float lo, hi;
    asm("mov.b64 {%0, %1}, %2;" : "=f"(lo), "=f"(hi) : "l"(v));
    return make_float2(lo, hi);
}
__device__ __forceinline__ ull ffma2(ull a, ull b, ull c) {
    ull d;
    asm("fma.rn.f32x2 %0, %1, %2, %3;" : "=l"(d) : "l"(a), "l"(b), "l"(c));
    return d;
}

// Register-resident Gauss-Jordan inverse of SPD 32x32: lane tid owns row tid.
// buf = 32-float, 16B-aligned smem scratch for pivot-row broadcast.
__device__ __forceinline__ void gj_inv_reg(float row[32], float* buf, int tid) {
#pragma unroll
    for (int k = 0; k < 32; ++k) {
        if (tid == k) {
            float4* b4 = reinterpret_cast<float4*>(buf);
#pragma unroll
            for (int q = 0; q < 8; q++)
                b4[q] = make_float4(row[4 * q], row[4 * q + 1], row[4 * q + 2], row[4 * q + 3]);
        }
        __syncwarp();
        float rk[32];
        {
            const float4* b4 = reinterpret_cast<const float4*>(buf);
#pragma unroll
            for (int q = 0; q < 8; q++) {
                float4 v = b4[q];
                rk[4 * q] = v.x; rk[4 * q + 1] = v.y; rk[4 * q + 2] = v.z; rk[4 * q + 3] = v.w;
            }
        }
        __syncwarp();
        float piv = 1.0f / rk[k];
        float f = (row[k] - ((tid == k) ? 1.0f : 0.0f)) * piv;
#pragma unroll
        for (int j = 0; j < 32; ++j)
            row[j] = fmaf(-f, rk[j], row[j]);
        row[k] = (tid == k) ? piv : -f;
    }
}

__global__ void __launch_bounds__(128, 4)
fw_kernel(const float* __restrict__ x_raw, const float* __restrict__ Ain,
          const float* __restrict__ bin, const float* __restrict__ W1,
          const float* __restrict__ b1v, const float* __restrict__ w2,
          float* __restrict__ out, int P)
{
    __shared__ __align__(16) float smem_all[4 * WARPF];
    const int tid = threadIdx.x & 31;
    const int wid = threadIdx.x >> 5;
    const int p = blockIdx.x * 4 + wid;
    if (p >= P) return;
    float* sw = smem_all + wid * WARPF;

    // ------------------------------------------------------------------
    // Load A (smem rows + packed lane-column apk), b, x_raw
    // ------------------------------------------------------------------
    ull apk[12];   // packed pairs (A[2j][tid], A[2j+1][tid])
    {
        float tmpA[MCc];
        const float* Ap = Ain + (size_t)p * (MCc * NVc);
#pragma unroll
        for (int r = 0; r < MCc; r++) {
            float v = Ap[r * NVc + tid];
            sw[OFF_A + r * 36 + tid] = v;
            tmpA[r] = v;
        }
#pragma unroll
        for (int j = 0; j < 12; j++) apk[j] = pk2(tmpA[2 * j], tmpA[2 * j + 1]);
    }
    const float b_own = (tid < MCc) ? bin[(size_t)p * MCc + tid] : 0.0f;
    const float xr = x_raw[(size_t)p * NVc + tid];
    __syncwarp();

    float xf_own = 0.0f, u_own = 0.0f, g_own = 0.0f;

    // ==================================================================
    //  phase 0: anchor QP (Schur-reduced, Ks = A_h^T A_h + .75 A_s^T A_s + 2I)
    //  phase 1: LMO LP   (K = A^T A + I), preceded by the critic gradient
    // ==================================================================
#pragma unroll 1
    for (int phase = 0; phase < 2; ++phase) {
        if (phase == 1) {
            // ----------------------------------------------------------
            // Gradient of critic: g = W1 @ (w2 * (1 - tanh^2(x W1 + b1)))
            // ----------------------------------------------------------
            float gp[32];
#pragma unroll
            for (int j = 0; j < 32; j++) gp[j] = 0.0f;
#pragma unroll 1
            for (int hb = 0; hb < 8; ++hb) {
                int h = hb * 32 + tid;
                float col[32];
#pragma unroll
                for (int j = 0; j < 32; j++) col[j] = W1[j * 256 + h];
                float z0 = b1v[h], z1 = 0.0f;
                const float4* x4 = reinterpret_cast<const float4*>(sw + OFF_U);
#pragma unroll
                for (int q = 0; q < 8; q++) {
                    float4 xv = x4[q];
                    float s = xv.x * col[4 * q] + xv.y * col[4 * q + 1]
                            + xv.z * col[4 * q + 2] + xv.w * col[4 * q + 3];
                    if (q & 1) z1 += s; else z0 += s;
                }
                float th = tanhf(z0 + z1);
                float v = w2[h] * (1.0f - th * th);
#pragma unroll
                for (int j = 0; j < 32; j++) gp[j] = fmaf(v, col[j], gp[j]);
            }
            __syncwarp();
            {
                float4* md = reinterpret_cast<float4*>(sw + OFF_M + tid * 36);
#pragma unroll
                for (int q = 0; q < 8; q++)
                    md[q] = make_float4(gp[4 * q], gp[4 * q + 1], gp[4 * q + 2], gp[4 * q + 3]);
            }
            __syncwarp();
            float gs0 = 0.0f, gs1 = 0.0f;
#pragma unroll
            for (int i = 0; i < 32; i++) {
                float v = sw[OFF_M + i * 36 + tid];
                if (i & 1) gs1 += v; else gs0 += v;
            }
            g_own = gs0 + gs1;
            __syncwarp();   // OFF_M reads done before it is overwritten below
        }

        // --------------------------------------------------------------
        // Build K row in registers (a read from smem), invert in regs
        // --------------------------------------------------------------
        float mrow[32];
        {
            const float dg = (phase == 0) ? 2.0f : 1.0f;
            const float ws = (phase == 0) ? 0.75f : 1.0f;
#pragma unroll
            for (int e = 0; e < 32; e++) mrow[e] = (tid == e) ? dg : 0.0f;
#pragma unroll
            for (int r = 0; r < MCc; r++) {
                float a = sw[OFF_A + r * 36 + tid];
                if (r >= MHc) a *= ws;
                const float4* ar = reinterpret_cast<const float4*>(sw + OFF_A + r * 36);
#pragma unroll
                for (int q = 0; q < 8; q++) {
                    float4 v = ar[q];
                    mrow[4 * q + 0] = fmaf(a, v.x, mrow[4 * q + 0]);
                    mrow[4 * q + 1] = fmaf(a, v.y, mrow[4 * q + 1]);
                    mrow[4 * q + 2] = fmaf(a, v.z, mrow[4 * q + 2]);
                    mrow[4 * q + 3] = fmaf(a, v.w, mrow[4 * q + 3]);
                }
            }
        }

        gj_inv_reg(mrow, sw + OFF_R, tid);   // mrow = Kinv row tid

        // write Kinv rows to smem once (GM build needs all rows)
        {
            float4* md = reinterpret_cast<float4*>(sw + OFF_M + tid * 36);
#pragma unroll
            for (int q = 0; q < 8; q++)
                md[q] = make_float4(mrow[4 * q], mrow[4 * q + 1], mrow[4 * q + 2], mrow[4 * q + 3]);
        }
        __syncwarp();

        // --------------------------------------------------------------
        // GM row = coef * (A_src * Kinv)
        // --------------------------------------------------------------
        float GM[32];
        {
            bool act; float coef; int src;
            if (phase == 0) {
                act = (tid < 28);
                coef = (tid < MHc) ? 1.0f : (tid < MCc) ? 0.75f : -0.25f;
                src = (tid < MCc) ? tid : tid - 4;
            } else {
                act = (tid < MCc);
                coef = 1.0f;
                src = tid;
            }
#pragma unroll
            for (int e = 0; e < 32; e++) GM[e] = 0.0f;
#pragma unroll 1
            for (int jb = 0; jb < 8; jb++) {
                float4 av = make_float4(0.f, 0.f, 0.f, 0.f);
                if (act)
                    av = reinterpret_cast<const float4*>(sw + OFF_A + src * 36)[jb];
                av.x *= coef; av.y *= coef; av.z *= coef; av.w *= coef;
#pragma unroll
                for (int c = 0; c < 4; c++) {
                    int j = 4 * jb + c;
                    float a = (c == 0) ? av.x : (c == 1) ? av.y : (c == 2) ? av.z : av.w;
                    const float4* mrw = reinterpret_cast<const float4*>(sw + OFF_M + j * 36);
#pragma unroll
                    for (int q = 0; q < 8; q++) {
                        float4 v = mrw[q];
                        GM[4 * q + 0] = fmaf(a, v.x, GM[4 * q + 0]);
                        GM[4 * q + 1] = fmaf(a, v.y, GM[4 * q + 1]);
                        GM[4 * q + 2] = fmaf(a, v.z, GM[4 * q + 2]);
                        GM[4 * q + 3] = fmaf(a, v.w, GM[4 * q + 3]);
                    }
                }
            }
        }

        // pack Kinv row + GM row into f32x2 pairs; scalars die here
        ull mpk[16], gpk[16];
#pragma unroll
        for (int c = 0; c < 16; c++) {
            mpk[c] = pk2(mrow[2 * c], mrow[2 * c + 1]);
            gpk[c] = pk2(GM[2 * c], GM[2 * c + 1]);
        }

        // --------------------------------------------------------------
        // ADMM loops (packed FFMA2 dots)
        // --------------------------------------------------------------
        if (phase == 0) {
            // Anchor: rows 0..27 (y1,t1) on lanes 0..27; rows 28..59 per-lane.
            // T[0..23] stores prescaled t: T[r]=t1[r] (r<20),
            // T[20+k]=0.75 t1[20+k]-0.25 t1[24+k] (slack-folded column coef).
            // gu slack correction for lanes 20..27 kept in slack_corr.
            float y1 = 0.0f, t1o = 0.0f, y3 = 0.0f, t3o = 0.0f;
            u_own = 0.0f;
            const float h1 = (tid < MCc) ? b_own : 0.0f;
            if (tid < MCc) sw[OFF_T + tid] = 0.0f;
            float slack_corr = 0.0f;
#pragma unroll 1
            for (int it = 0; it <= ITc; ++it) {
                __syncwarp();
                {
                    const ulonglong2* t2 = reinterpret_cast<const ulonglong2*>(sw + OFF_T);
                    ull ac0 = 0ull, ac1 = 0ull;
#pragma unroll
                    for (int q = 0; q < 6; q++) {
                        ulonglong2 tv = t2[q];
                        ac0 = ffma2(apk[2 * q], tv.x, ac0);
                        ac1 = ffma2(apk[2 * q + 1], tv.y, ac1);
                    }
                    float2 s0 = upk2(ac0), s1 = upk2(ac1);
                    sw[OFF_R + tid] = xr + s0.x + s0.y + s1.x + s1.y - t3o;
                }
                __syncwarp();
                float gu;
                {
                    const ulonglong2* rv2 = reinterpret_cast<const ulonglong2*>(sw + OFF_R);
                    ull au0 = 0ull, au1 = 0ull, ag0 = 0ull, ag1 = 0ull;
#pragma unroll
                    for (int q = 0; q < 8; q++) {
                        ulonglong2 rv = rv2[q];
                        au0 = ffma2(mpk[2 * q], rv.x, au0);
                        au1 = ffma2(mpk[2 * q + 1], rv.y, au1);
                        ag0 = ffma2(gpk[2 * q], rv.x, ag0);
                        ag1 = ffma2(gpk[2 * q + 1], rv.y, ag1);
                    }
                    float2 ua = upk2(au0), ub = upk2(au1), ga = upk2(ag0), gb = upk2(ag1);
                    u_own = ua.x + ua.y + ub.x + ub.y;
                    gu = ga.x + ga.y + gb.x + gb.y + slack_corr;
                }
                if (it == ITc) break;
                float w = gu + y1;
                float z = fminf(w, h1);
                y1 = w - z;
                t1o = z - y1;
                // shfl pair: lane 20+k gets t1[24+k]; lane 24+k gets t1[20+k]
                float td = __shfl_down_sync(0xffffffffu, t1o, 4);
                float tu = __shfl_up_sync(0xffffffffu, t1o, 4);
                float sv = t1o;
                slack_corr = 0.0f;
                if (tid >= MHc && tid < MCc) {
                    sv = 0.75f * t1o - 0.25f * td;
                    slack_corr = 0.25f * (t1o + td);
                } else if (tid >= MCc && tid < 28) {
                    slack_corr = 0.25f * (tu + t1o);
                }
                if (tid < MCc) sw[OFF_T + tid] = sv;
                float w3 = y3 - u_own;
                float z3 = fminf(w3, 0.0f);
                y3 = w3 - z3;
                t3o = z3 - y3;
            }
            xf_own = u_own;
            sw[OFF_U + tid] = u_own;
            __syncwarp();
        } else {
            // LMO: rows 0..23 (A, h=b) on lanes 0..23; rows 24..55 per-lane
            float y1 = 0.0f, t1o = 0.0f, y3 = 0.0f, t3o = 0.0f;
            u_own = 0.0f;
            if (tid < MCc) sw[OFF_T + tid] = 0.0f;
#pragma unroll 1
            for (int it = 0; it <= ITc; ++it) {
                __syncwarp();
                {
                    const ulonglong2* t2 = reinterpret_cast<const ulonglong2*>(sw + OFF_T);
                    ull ac0 = 0ull, ac1 = 0ull;
#pragma unroll
                    for (int q = 0; q < 6; q++) {
                        ulonglong2 tv = t2[q];
                        ac0 = ffma2(apk[2 * q], tv.x, ac0);
                        ac1 = ffma2(apk[2 * q + 1], tv.y, ac1);
                    }
                    float2 s0 = upk2(ac0), s1 = upk2(ac1);
                    sw[OFF_R + tid] = g_own + s0.x + s0.y + s1.x + s1.y - t3o;
                }
                __syncwarp();
                {
                    const ulonglong2* rv2 = reinterpret_cast<const ulonglong2*>(sw + OFF_R);
                    ull au0 = 0ull, au1 = 0ull, ag0 = 0ull, ag1 = 0ull;
#pragma unroll
                    for (int q = 0; q < 8; q++) {
                        ulonglong2 rv = rv2[q];
                        au0 = ffma2(mpk[2 * q], rv.x, au0);
                        au1 = ffma2(mpk[2 * q + 1], rv.y, au1);
                        ag0 = ffma2(gpk[2 * q], rv.x, ag0);
                        ag1 = ffma2(gpk[2 * q + 1], rv.y, ag1);
                    }
                    float2 ua = upk2(au0), ub = upk2(au1), ga = upk2(ag0), gb = upk2(ag1);
                    u_own = ua.x + ua.y + ub.x + ub.y;
                    float gu = ga.x + ga.y + gb.x + gb.y;
                    if (it == ITc) break;
                    float w = gu + y1;
                    float z = fminf(w, b_own);
                    y1 = w - z;
                    t1o = z - y1;
                    if (tid < MCc) sw[OFF_T + tid] = t1o;
                    float w3 = y3 - u_own;
                    float z3 = fminf(w3, 0.0f);
                    y3 = w3 - z3;
                    t3o = z3 - y3;
                }
            }
        }
    }

    // Frank-Wolfe blend
    out[(size_t)p * NVc + tid] = 0.9f * xf_own + 0.1f * u_own;
}

}  // namespace

extern "C" void kernel_launch(void* const* d_in, const int* in_sizes, int n_in,
                              void* d_out, int out_size) {
    const float* x_raw = (const float*)d_in[0];
    const float* A     = (const float*)d_in[1];
    const float* b     = (const float*)d_in[2];
    const float* W1    = (const float*)d_in[3];
    const float* b1v   = (const float*)d_in[4];
    const float* w2    = (const float*)d_in[5];
    float* out = (float*)d_out;
    int P = in_sizes[0] / 32;           // number of flattened problems
    int blocks = (P + 3) / 4;           // 4 problems (warps) per block
    fw_kernel<<<blocks, 128>>>(x_raw, A, b, W1, b1v, w2, out, P);
}